// round 12
// baseline (speedup 1.0000x reference)
#include <cuda_runtime.h>
#include <cuda_fp16.h>
#include <cuda_bf16.h>

// Problem constants (fixed by the reference).
#define U_CNT 100000
#define I_CNT 100000
#define N_CNT 200000           // U + I
#define L_LAYERS 3
#define ROW_F4 16              // D/4 float4 per node row (fp32 inputs)
#define ROW_H4 8               // 8 uint4 per node row (64 halves, 128B)
#define NH4   (N_CNT * ROW_H4) // 1.6M uint4 = 25.6 MB per layer buffer
#define E_MAX 6400000
#define SCAN_BLK 1024
#define SCAN_NB ((N_CNT + SCAN_BLK - 1) / SCAN_BLK)   // 196
#define DBINS 256
#define SPMM_U_BLOCKS ((U_CNT * 8 + 255) / 256)       // 3125
#define SEL_MAX 32768          // max unique selected rows (2 * B)

// val quantization: val in [0, 1/32), 14-bit fixed point in bits [18,32).
#define VAL_ENC_SCALE (32.0f * 16383.0f)
#define VAL_DEC_SCALE (1.0f / (32.0f * 16383.0f))

// Scratch (__device__ globals only — allocation-free rule).
// Steady-state invariants maintained across calls (zero-init by loader first):
//   g_deg    == 0 on entry (re-zeroed in k_scan3)
//   g_dbin   == 0 on entry (re-zeroed in k_scatU_init — BOTH partitions)
//   g_tick   == 0 on entry (re-zeroed by scan1's last block)
//   g_flag   == 0 on entry (re-zeroed in k_spmm3_sel for selected rows)
//   g_selcnt == 0 on entry (re-zeroed in k_dot)
__device__ uint4    g_Lh[L_LAYERS + 1][NH4];   // 4 x 25.6 MB fp16 layer buffers
__device__ uint4    g_sem[NH4];                // fp16 semantic (symptom|herb) table
__device__ unsigned g_csr [E_MAX];             // packed (col | q<<18), grouped by row
__device__ int      g_deg [N_CNT];
__device__ int      g_ptr [N_CNT + 1];
__device__ int      g_cursor[N_CNT];
__device__ int      g_bsum[SCAN_NB];
__device__ int      g_dbin[2][DBINS];          // degree bins: [0]=users, [1]=items
__device__ int      g_order[N_CNT];            // users desc-deg in [0,U), items in [U,N)
__device__ int      g_tick;
__device__ int      g_flag[N_CNT];             // selected-row dedupe flags
__device__ int      g_sel [SEL_MAX];           // unique selected rows (layer-3 targets)
__device__ int      g_selcnt;

__device__ __forceinline__ float sigm(float x) { return 1.0f / (1.0f + __expf(-x)); }

__device__ __forceinline__ uint4 pack8(const float* x)
{
    uint4 r;
    half2 h0 = __floats2half2_rn(x[0], x[1]);
    half2 h1 = __floats2half2_rn(x[2], x[3]);
    half2 h2 = __floats2half2_rn(x[4], x[5]);
    half2 h3 = __floats2half2_rn(x[6], x[7]);
    r.x = *(unsigned*)&h0; r.y = *(unsigned*)&h1;
    r.z = *(unsigned*)&h2; r.w = *(unsigned*)&h3;
    return r;
}

__device__ __forceinline__ void unpack8(uint4 q, float* x)
{
    half2* hp = (half2*)&q;
    float2 f0 = __half22float2(hp[0]);
    float2 f1 = __half22float2(hp[1]);
    float2 f2 = __half22float2(hp[2]);
    float2 f3 = __half22float2(hp[3]);
    x[0] = f0.x; x[1] = f0.y; x[2] = f1.x; x[3] = f1.y;
    x[4] = f2.x; x[5] = f2.y; x[6] = f3.x; x[7] = f3.y;
}

__device__ __forceinline__ void acc8(float* acc, uint4 q, float v)
{
    float x[8];
    unpack8(q, x);
    #pragma unroll
    for (int k = 0; k < 8; k++) acc[k] = fmaf(v, x[k], acc[k]);
}

// Shared SpMM row body: gather+accumulate row `rw` of `layer`, mix, store.
__device__ __forceinline__ void spmm_row_do(int layer, int rw, int sub,
                                            const float* __restrict__ ulw,
                                            const float* __restrict__ ilw)
{
    const uint4* __restrict__ src = g_Lh[layer - 1];
    uint4*       __restrict__ dst = g_Lh[layer];

    int start = __ldg(&g_ptr[rw]);
    int end   = __ldg(&g_ptr[rw + 1]);

    float acc[8];
    #pragma unroll
    for (int k = 0; k < 8; k++) acc[k] = 0.0f;

    int j = start;
    for (; j + 4 <= end; j += 4) {
        unsigned e0 = __ldg(&g_csr[j + 0]);
        unsigned e1 = __ldg(&g_csr[j + 1]);
        unsigned e2 = __ldg(&g_csr[j + 2]);
        unsigned e3 = __ldg(&g_csr[j + 3]);
        uint4 q0 = __ldg(&src[(e0 & 0x3FFFFu) * ROW_H4 + sub]);
        uint4 q1 = __ldg(&src[(e1 & 0x3FFFFu) * ROW_H4 + sub]);
        uint4 q2 = __ldg(&src[(e2 & 0x3FFFFu) * ROW_H4 + sub]);
        uint4 q3 = __ldg(&src[(e3 & 0x3FFFFu) * ROW_H4 + sub]);
        acc8(acc, q0, (float)(e0 >> 18) * VAL_DEC_SCALE);
        acc8(acc, q1, (float)(e1 >> 18) * VAL_DEC_SCALE);
        acc8(acc, q2, (float)(e2 >> 18) * VAL_DEC_SCALE);
        acc8(acc, q3, (float)(e3 >> 18) * VAL_DEC_SCALE);
    }
    for (; j < end; j++) {
        unsigned e0 = __ldg(&g_csr[j]);
        uint4 q0 = __ldg(&src[(e0 & 0x3FFFFu) * ROW_H4 + sub]);
        acc8(acc, q0, (float)(e0 >> 18) * VAL_DEC_SCALE);
    }

    float a = (rw < U_CNT) ? sigm(__ldg(ulw + layer)) : sigm(__ldg(ilw + layer));

    float o[8];
    unpack8(__ldg(&g_sem[rw * ROW_H4 + sub]), o);

    float x[8];
    #pragma unroll
    for (int k = 0; k < 8; k++) x[k] = a * acc[k] + (1.0f - a) * o[k];

    __stcs(&dst[rw * ROW_H4 + sub], pack8(x));
}

// ---------------------------------------------------------------------------
// Degree histogram (fire-and-forget REDG, 4 edges/thread) + selected-row
// marking: dedupe users/items into g_sel (layer-3 target list).
// ---------------------------------------------------------------------------
__global__ void k_hist_mark(const int* __restrict__ row, int E,
                            const int* __restrict__ users,
                            const int* __restrict__ items, int B)
{
    int i = blockIdx.x * blockDim.x + threadIdx.x;

    if (i < B) {
        int u = __ldg(users + i);
        if (atomicExch(&g_flag[u], 1) == 0) {
            int pos = atomicAdd(&g_selcnt, 1);
            if (pos < SEL_MAX) g_sel[pos] = u;
        }
        int it = __ldg(items + i) + U_CNT;
        if (atomicExch(&g_flag[it], 1) == 0) {
            int pos = atomicAdd(&g_selcnt, 1);
            if (pos < SEL_MAX) g_sel[pos] = it;
        }
    }

    int e0 = i * 4;
    if (e0 + 3 < E) {
        int4 r4 = __ldg((const int4*)(row + e0));
        atomicAdd(&g_deg[r4.x], 1);
        atomicAdd(&g_deg[r4.y], 1);
        atomicAdd(&g_deg[r4.z], 1);
        atomicAdd(&g_deg[r4.w], 1);
    } else if (e0 < E) {
        for (int e = e0; e < E; e++) atomicAdd(&g_deg[__ldg(row + e)], 1);
    }
}

// ---------------------------------------------------------------------------
// Scan 1: warp-shuffle block scan of degrees + per-partition degree bins.
// Last finished block scans the 196 block sums AND both 256-entry bin sets.
// ---------------------------------------------------------------------------
__global__ void k_scan1()
{
    __shared__ int sw[32];
    __shared__ int sbuf[256];
    __shared__ int isLast;
    int i    = blockIdx.x * SCAN_BLK + threadIdx.x;
    int lane = threadIdx.x & 31;
    int wid  = threadIdx.x >> 5;

    int v = (i < N_CNT) ? g_deg[i] : 0;

    int x = v;
    #pragma unroll
    for (int off = 1; off < 32; off <<= 1) {
        int y = __shfl_up_sync(0xffffffffu, x, off);
        if (lane >= off) x += y;
    }
    if (lane == 31) sw[wid] = x;
    __syncthreads();

    if (wid == 0) {
        int wv = sw[lane];
        int wx = wv;
        #pragma unroll
        for (int off = 1; off < 32; off <<= 1) {
            int y = __shfl_up_sync(0xffffffffu, wx, off);
            if (lane >= off) wx += y;
        }
        sw[lane] = wx - wv;
    }
    __syncthreads();

    int incl = x + sw[wid];
    if (i < N_CNT) g_ptr[i] = incl - v;             // exclusive, block-local
    if (threadIdx.x == SCAN_BLK - 1) g_bsum[blockIdx.x] = incl;

    if (i < N_CNT) {
        int d = v < DBINS ? v : DBINS - 1;
        atomicAdd(&g_dbin[i < U_CNT ? 0 : 1][d], 1);
    }

    __threadfence();
    if (threadIdx.x == 0)
        isLast = (atomicAdd(&g_tick, 1) == (int)gridDim.x - 1);
    __syncthreads();
    if (!isLast) return;

    int t = threadIdx.x;

    int v2 = (t < SCAN_NB) ? g_bsum[t] : 0;
    if (t < 256) sbuf[t] = v2;
    __syncthreads();
    for (int off = 1; off < 256; off <<= 1) {
        int u = (t < 256 && t >= off) ? sbuf[t - off] : 0;
        __syncthreads();
        if (t < 256) sbuf[t] += u;
        __syncthreads();
    }
    if (t < SCAN_NB) g_bsum[t] = sbuf[t] - v2;
    if (t == SCAN_NB - 1) g_ptr[N_CNT] = sbuf[t];
    __syncthreads();

    #pragma unroll
    for (int part = 0; part < 2; part++) {
        int v3 = (t < DBINS) ? g_dbin[part][t] : 0;
        if (t < 256) sbuf[t] = v3;
        __syncthreads();
        for (int off = 1; off < 256; off <<= 1) {
            int u = (t < 256 && t >= off) ? sbuf[t - off] : 0;
            __syncthreads();
            if (t < 256) sbuf[t] += u;
            __syncthreads();
        }
        if (t < DBINS) g_dbin[part][t] = sbuf[t] - v3;
        __syncthreads();
    }

    if (t == 0) g_tick = 0;   // restore invariant
}

// ---------------------------------------------------------------------------
// Scan 3: finalize ptr/cursor; per-partition descending-degree counting sort
// (users -> g_order[0,U), items -> g_order[U,N)). Re-zero g_deg (invariant).
// ---------------------------------------------------------------------------
__global__ void k_scan3()
{
    int i = blockIdx.x * blockDim.x + threadIdx.x;
    if (i >= N_CNT) return;
    int p = g_ptr[i] + g_bsum[i / SCAN_BLK];
    g_ptr[i]    = p;
    g_cursor[i] = p;
    int d = g_deg[i];
    d = d < DBINS ? d : DBINS - 1;
    if (i < U_CNT) {
        int pos = atomicAdd(&g_dbin[0][d], 1);
        g_order[U_CNT - 1 - pos] = i;
    } else {
        int pos = atomicAdd(&g_dbin[1][d], 1);
        g_order[U_CNT + I_CNT - 1 - pos] = i;
    }
    g_deg[i] = 0;             // restore invariant
}

// ---------------------------------------------------------------------------
// FUSED user-edge scatter + init (layer-0 mix + fp16 sem table in the shadow
// of the atomic round-trips). Re-zeroes BOTH g_dbin partitions.
// ---------------------------------------------------------------------------
__global__ void k_scatU_init(const int*    __restrict__ row, const int* __restrict__ col,
                             const float*  __restrict__ val, int E,
                             const float4* __restrict__ ue, const float4* __restrict__ ie,
                             const float4* __restrict__ se, const float4* __restrict__ he,
                             const float*  __restrict__ ulw, const float* __restrict__ ilw)
{
    int i = blockIdx.x * blockDim.x + threadIdx.x;
    if (blockIdx.x == 0 && threadIdx.x < DBINS) {
        ((int*)g_dbin)[threadIdx.x]         = 0;   // user bins
        ((int*)g_dbin)[threadIdx.x + DBINS] = 0;   // item bins
    }

    int e0 = i * 4;
    bool full = (e0 + 3 < E);
    int p[4], c[4];
    float v[4];
    bool m[4];
    if (full) {
        int4   r4 = __ldg((const int4*)(row + e0));
        int4   c4 = __ldg((const int4*)(col + e0));
        float4 v4 = __ldg((const float4*)(val + e0));
        int r[4] = { r4.x, r4.y, r4.z, r4.w };
        c[0] = c4.x; c[1] = c4.y; c[2] = c4.z; c[3] = c4.w;
        v[0] = v4.x; v[1] = v4.y; v[2] = v4.z; v[3] = v4.w;
        #pragma unroll
        for (int k = 0; k < 4; k++) {
            m[k] = (r[k] < U_CNT);
            p[k] = m[k] ? atomicAdd(&g_cursor[r[k]], 1) : 0;
        }
    }

    if (i < NH4) {
        int rw  = i >> 3;
        int sub = i & 7;

        const float4* base;
        const float4* sem;
        int r;
        float a;
        if (rw < U_CNT) { a = sigm(__ldg(ulw)); base = ue; sem = se; r = rw; }
        else            { a = sigm(__ldg(ilw)); base = ie; sem = he; r = rw - U_CNT; }

        float4 b0 = __ldcs(&base[r * ROW_F4 + sub * 2]);
        float4 b1 = __ldcs(&base[r * ROW_F4 + sub * 2 + 1]);
        float4 s0 = __ldcs(&sem [r * ROW_F4 + sub * 2]);
        float4 s1 = __ldcs(&sem [r * ROW_F4 + sub * 2 + 1]);

        float xs[8] = { s0.x, s0.y, s0.z, s0.w, s1.x, s1.y, s1.z, s1.w };
        float xb[8] = { b0.x, b0.y, b0.z, b0.w, b1.x, b1.y, b1.z, b1.w };
        float x[8];
        #pragma unroll
        for (int k = 0; k < 8; k++) x[k] = a * xb[k] + (1.0f - a) * xs[k];

        g_sem[i]   = pack8(xs);
        g_Lh[0][i] = pack8(x);
    }

    if (full) {
        #pragma unroll
        for (int k = 0; k < 4; k++) {
            if (m[k]) {
                int q = __float2int_rn(v[k] * VAL_ENC_SCALE);
                q = q < 16383 ? q : 16383;
                __stcs(&g_csr[p[k]], (unsigned)c[k] | ((unsigned)q << 18));
            }
        }
    } else if (e0 < E) {
        for (int e = e0; e < E; e++) {
            int r = __ldg(row + e);
            if (r >= U_CNT) continue;
            int pp = atomicAdd(&g_cursor[r], 1);
            int q = __float2int_rn(__ldg(val + e) * VAL_ENC_SCALE);
            q = q < 16383 ? q : 16383;
            __stcs(&g_csr[pp], (unsigned)__ldg(col + e) | ((unsigned)q << 18));
        }
    }
}

// ---------------------------------------------------------------------------
// FUSED: spmm layer-1 over USER rows  ∥  scatter of ITEM edges.
// Role by bid: bid%3==0 && bid/3 < SPMM_U_BLOCKS -> spmm; else scatter with
// sb = bid - min(ceil(bid/3), SPMM_U_BLOCKS).
// ---------------------------------------------------------------------------
__global__ void k_spmmU1_scatI(const int*   __restrict__ row, const int* __restrict__ col,
                               const float* __restrict__ val, int E,
                               const float* __restrict__ ulw, const float* __restrict__ ilw)
{
    int bid = blockIdx.x;
    bool is_spmm = (bid % 3 == 0) && (bid / 3 < SPMM_U_BLOCKS);
    if (is_spmm) {
        int t = (bid / 3) * blockDim.x + threadIdx.x;
        int g = t >> 3;
        if (g >= U_CNT) return;
        int sub = t & 7;
        int rw = __ldg(&g_order[g]);
        spmm_row_do(1, rw, sub, ulw, ilw);
        return;
    }
    int nsp = (bid + 2) / 3;
    if (nsp > SPMM_U_BLOCKS) nsp = SPMM_U_BLOCKS;
    int sb = bid - nsp;
    int i = sb * blockDim.x + threadIdx.x;

    int e0 = i * 4;
    if (e0 >= E) return;
    if (e0 + 3 < E) {
        int4   r4 = __ldg((const int4*)(row + e0));
        int4   c4 = __ldg((const int4*)(col + e0));
        float4 v4 = __ldg((const float4*)(val + e0));
        int r[4] = { r4.x, r4.y, r4.z, r4.w };
        int c[4] = { c4.x, c4.y, c4.z, c4.w };
        float v[4] = { v4.x, v4.y, v4.z, v4.w };
        int p[4];
        bool m[4];
        #pragma unroll
        for (int k = 0; k < 4; k++) {
            m[k] = (r[k] >= U_CNT);
            p[k] = m[k] ? atomicAdd(&g_cursor[r[k]], 1) : 0;
        }
        #pragma unroll
        for (int k = 0; k < 4; k++) {
            if (m[k]) {
                int q = __float2int_rn(v[k] * VAL_ENC_SCALE);
                q = q < 16383 ? q : 16383;
                __stcs(&g_csr[p[k]], (unsigned)c[k] | ((unsigned)q << 18));
            }
        }
    } else {
        for (int e = e0; e < E; e++) {
            int r = __ldg(row + e);
            if (r < U_CNT) continue;
            int pp = atomicAdd(&g_cursor[r], 1);
            int q = __float2int_rn(__ldg(val + e) * VAL_ENC_SCALE);
            q = q < 16383 ? q : 16383;
            __stcs(&g_csr[pp], (unsigned)__ldg(col + e) | ((unsigned)q << 18));
        }
    }
}

// ---------------------------------------------------------------------------
// SpMM layer-1 over ITEM rows only.
// ---------------------------------------------------------------------------
__global__ void k_spmmI1(const float* __restrict__ ulw, const float* __restrict__ ilw)
{
    int t = blockIdx.x * blockDim.x + threadIdx.x;
    int g = t >> 3;
    if (g >= I_CNT) return;
    int sub = t & 7;
    int rw = __ldg(&g_order[U_CNT + g]);
    spmm_row_do(1, rw, sub, ulw, ilw);
}

// ---------------------------------------------------------------------------
// Full SpMM (layer 2) over all rows.
// ---------------------------------------------------------------------------
__global__ void k_spmm_fused(const float* __restrict__ ulw, const float* __restrict__ ilw,
                             int layer)
{
    int t = blockIdx.x * blockDim.x + threadIdx.x;
    int g = t >> 3;
    if (g >= N_CNT) return;
    int sub = t & 7;
    int rw = __ldg(&g_order[g]);
    spmm_row_do(layer, rw, sub, ulw, ilw);
}

// ---------------------------------------------------------------------------
// SELECTIVE SpMM layer 3: only rows the final dot will read (<= 32768).
// Also restores the g_flag invariant for its rows.
// ---------------------------------------------------------------------------
__global__ void k_spmm3_sel(const float* __restrict__ ulw, const float* __restrict__ ilw)
{
    int t = blockIdx.x * blockDim.x + threadIdx.x;
    int g = t >> 3;
    if (g >= g_selcnt) return;
    int sub = t & 7;
    int rw = g_sel[g];
    spmm_row_do(L_LAYERS, rw, sub, ulw, ilw);
    if (sub == 0) g_flag[rw] = 0;   // restore invariant
}

// ---------------------------------------------------------------------------
// Final dot: 8 lanes per (user, item) pair; sum 4 layer rows in fp32.
// Resets g_selcnt (runs strictly after k_spmm3_sel).
// ---------------------------------------------------------------------------
__global__ void k_dot(const int* __restrict__ users, const int* __restrict__ items,
                      float* __restrict__ out, int B)
{
    if (blockIdx.x == 0 && threadIdx.x == 0) g_selcnt = 0;   // restore invariant

    int t = blockIdx.x * blockDim.x + threadIdx.x;
    int b = t >> 3;
    if (b >= B) return;
    int sub = t & 7;

    int u  = __ldg(users + b);
    int it = __ldg(items + b);

    float su[8], si[8];
    #pragma unroll
    for (int k = 0; k < 8; k++) { su[k] = 0.0f; si[k] = 0.0f; }

    #pragma unroll
    for (int l = 0; l <= L_LAYERS; l++) {
        float xu[8], xi[8];
        unpack8(__ldg(&g_Lh[l][u * ROW_H4 + sub]), xu);
        unpack8(__ldg(&g_Lh[l][(U_CNT + it) * ROW_H4 + sub]), xi);
        #pragma unroll
        for (int k = 0; k < 8; k++) { su[k] += xu[k]; si[k] += xi[k]; }
    }

    float s = 0.0f;
    #pragma unroll
    for (int k = 0; k < 8; k++) s = fmaf(su[k], si[k], s);

    s += __shfl_down_sync(0xffffffffu, s, 4, 8);
    s += __shfl_down_sync(0xffffffffu, s, 2, 8);
    s += __shfl_down_sync(0xffffffffu, s, 1, 8);

    if (sub == 0) out[b] = s * (1.0f / ((L_LAYERS + 1) * (L_LAYERS + 1)));
}

// ---------------------------------------------------------------------------
// Launch sequence: hist+mark | scan1 | scan3 | scatU+init | spmmU1∥scatI |
// spmmI1 | spmm2 | spmm3_sel | dot.
// ---------------------------------------------------------------------------
extern "C" void kernel_launch(void* const* d_in, const int* in_sizes, int n_in,
                              void* d_out, int out_size)
{
    const float4* user_emb    = (const float4*)d_in[0];
    const float4* item_emb    = (const float4*)d_in[1];
    const float4* symptom_emb = (const float4*)d_in[2];
    const float4* herb_emb    = (const float4*)d_in[3];
    const float*  user_lw     = (const float*)d_in[4];
    const float*  item_lw     = (const float*)d_in[5];
    const float*  edge_val    = (const float*)d_in[6];
    const int*    edge_row    = (const int*)d_in[7];
    const int*    edge_col    = (const int*)d_in[8];
    const int*    users       = (const int*)d_in[9];
    const int*    items       = (const int*)d_in[10];

    int E = in_sizes[6];
    int B = in_sizes[9];

    const int TB = 256;
    int e4 = (E + 3) / 4;

    int hist_threads = (e4 > B ? e4 : B);
    k_hist_mark<<<(hist_threads + TB - 1) / TB, TB>>>(edge_row, E, users, items, B);
    k_scan1<<<SCAN_NB, SCAN_BLK>>>();
    k_scan3<<<(N_CNT + TB - 1) / TB, TB>>>();

    int si_threads = (e4 > NH4 ? e4 : NH4);
    k_scatU_init<<<(si_threads + TB - 1) / TB, TB>>>(
        edge_row, edge_col, edge_val, E,
        user_emb, item_emb, symptom_emb, herb_emb, user_lw, item_lw);

    int scat_blocks = (e4 + TB - 1) / TB;
    int k5_blocks = SPMM_U_BLOCKS + scat_blocks;
    int need_for_spmm = (SPMM_U_BLOCKS - 1) * 3 + 1;
    if (k5_blocks < need_for_spmm) k5_blocks = need_for_spmm;
    k_spmmU1_scatI<<<k5_blocks, TB>>>(edge_row, edge_col, edge_val, E,
                                      user_lw, item_lw);

    k_spmmI1<<<(I_CNT * 8 + TB - 1) / TB, TB>>>(user_lw, item_lw);

    k_spmm_fused<<<(N_CNT * 8 + TB - 1) / TB, TB>>>(user_lw, item_lw, 2);

    k_spmm3_sel<<<(SEL_MAX * 8) / TB, TB>>>(user_lw, item_lw);

    k_dot<<<(B * 8 + TB - 1) / TB, TB>>>(users, items, (float*)d_out, B);
}

// round 13
// speedup vs baseline: 1.3037x; 1.3037x over previous
#include <cuda_runtime.h>
#include <cuda_fp16.h>
#include <cuda_bf16.h>

// Problem constants (fixed by the reference).
#define U_CNT 100000
#define I_CNT 100000
#define N_CNT 200000           // U + I
#define L_LAYERS 3
#define ROW_F4 16              // D/4 float4 per node row (fp32 inputs)
#define ROW_H4 8               // 8 uint4 per node row (64 halves, 128B)
#define NH4   (N_CNT * ROW_H4) // 1.6M uint4 = 25.6 MB per layer buffer
#define E_MAX 6400000
#define SCAN_BLK 1024
#define SCAN_NB ((N_CNT + SCAN_BLK - 1) / SCAN_BLK)   // 196
#define DBINS 256
#define SPMM_U_BLOCKS ((U_CNT * 8 + 255) / 256)       // 3125

// val quantization: val in [0, 1/32), 14-bit fixed point in bits [18,32).
#define VAL_ENC_SCALE (32.0f * 16383.0f)
#define VAL_DEC_SCALE (1.0f / (32.0f * 16383.0f))

// Scratch (__device__ globals only — allocation-free rule).
// Steady-state invariants maintained across calls (zero-init by loader first):
//   g_deg  == 0 on entry (re-zeroed in k_scan3)
//   g_dbin == 0 on entry (re-zeroed in k_scatU_init — BOTH partitions)
//   g_tick == 0 on entry (re-zeroed by scan1's last block)
__device__ uint4    g_Lh[L_LAYERS + 1][NH4];   // fp16 layer buffers (0..2 used)
__device__ uint4    g_sem[NH4];                // fp16 semantic (symptom|herb) table
__device__ unsigned g_csr [E_MAX];             // packed (col | q<<18), grouped by row
__device__ int      g_deg [N_CNT];
__device__ int      g_ptr [N_CNT + 1];
__device__ int      g_cursor[N_CNT];
__device__ int      g_bsum[SCAN_NB];
__device__ int      g_dbin[2][DBINS];          // degree bins: [0]=users, [1]=items
__device__ int      g_order[N_CNT];            // users desc-deg in [0,U), items in [U,N)
__device__ int      g_tick;

__device__ __forceinline__ float sigm(float x) { return 1.0f / (1.0f + __expf(-x)); }

__device__ __forceinline__ uint4 pack8(const float* x)
{
    uint4 r;
    half2 h0 = __floats2half2_rn(x[0], x[1]);
    half2 h1 = __floats2half2_rn(x[2], x[3]);
    half2 h2 = __floats2half2_rn(x[4], x[5]);
    half2 h3 = __floats2half2_rn(x[6], x[7]);
    r.x = *(unsigned*)&h0; r.y = *(unsigned*)&h1;
    r.z = *(unsigned*)&h2; r.w = *(unsigned*)&h3;
    return r;
}

__device__ __forceinline__ void unpack8(uint4 q, float* x)
{
    half2* hp = (half2*)&q;
    float2 f0 = __half22float2(hp[0]);
    float2 f1 = __half22float2(hp[1]);
    float2 f2 = __half22float2(hp[2]);
    float2 f3 = __half22float2(hp[3]);
    x[0] = f0.x; x[1] = f0.y; x[2] = f1.x; x[3] = f1.y;
    x[4] = f2.x; x[5] = f2.y; x[6] = f3.x; x[7] = f3.y;
}

__device__ __forceinline__ void acc8(float* acc, uint4 q, float v)
{
    float x[8];
    unpack8(q, x);
    #pragma unroll
    for (int k = 0; k < 8; k++) acc[k] = fmaf(v, x[k], acc[k]);
}

// CSR gather-accumulate over src for row rw: acc += sum(val * src[col]).
__device__ __forceinline__ void gather_row(const uint4* __restrict__ src,
                                           int rw, int sub, float* acc)
{
    int start = __ldg(&g_ptr[rw]);
    int end   = __ldg(&g_ptr[rw + 1]);
    int j = start;
    for (; j + 4 <= end; j += 4) {
        unsigned e0 = __ldg(&g_csr[j + 0]);
        unsigned e1 = __ldg(&g_csr[j + 1]);
        unsigned e2 = __ldg(&g_csr[j + 2]);
        unsigned e3 = __ldg(&g_csr[j + 3]);
        uint4 q0 = __ldg(&src[(e0 & 0x3FFFFu) * ROW_H4 + sub]);
        uint4 q1 = __ldg(&src[(e1 & 0x3FFFFu) * ROW_H4 + sub]);
        uint4 q2 = __ldg(&src[(e2 & 0x3FFFFu) * ROW_H4 + sub]);
        uint4 q3 = __ldg(&src[(e3 & 0x3FFFFu) * ROW_H4 + sub]);
        acc8(acc, q0, (float)(e0 >> 18) * VAL_DEC_SCALE);
        acc8(acc, q1, (float)(e1 >> 18) * VAL_DEC_SCALE);
        acc8(acc, q2, (float)(e2 >> 18) * VAL_DEC_SCALE);
        acc8(acc, q3, (float)(e3 >> 18) * VAL_DEC_SCALE);
    }
    for (; j < end; j++) {
        unsigned e0 = __ldg(&g_csr[j]);
        uint4 q0 = __ldg(&src[(e0 & 0x3FFFFu) * ROW_H4 + sub]);
        acc8(acc, q0, (float)(e0 >> 18) * VAL_DEC_SCALE);
    }
}

// Shared SpMM row body: gather+accumulate row `rw` of `layer`, mix, store.
__device__ __forceinline__ void spmm_row_do(int layer, int rw, int sub,
                                            const float* __restrict__ ulw,
                                            const float* __restrict__ ilw)
{
    const uint4* __restrict__ src = g_Lh[layer - 1];
    uint4*       __restrict__ dst = g_Lh[layer];

    float acc[8];
    #pragma unroll
    for (int k = 0; k < 8; k++) acc[k] = 0.0f;
    gather_row(src, rw, sub, acc);

    float a = (rw < U_CNT) ? sigm(__ldg(ulw + layer)) : sigm(__ldg(ilw + layer));

    float o[8];
    unpack8(__ldg(&g_sem[rw * ROW_H4 + sub]), o);

    float x[8];
    #pragma unroll
    for (int k = 0; k < 8; k++) x[k] = a * acc[k] + (1.0f - a) * o[k];

    __stcs(&dst[rw * ROW_H4 + sub], pack8(x));
}

// ---------------------------------------------------------------------------
// Degree histogram: fire-and-forget REDG atomics, 4 edges/thread.
// ---------------------------------------------------------------------------
__global__ void k_hist(const int* __restrict__ row, int E)
{
    int i = blockIdx.x * blockDim.x + threadIdx.x;
    int e0 = i * 4;
    if (e0 + 3 < E) {
        int4 r4 = __ldg((const int4*)(row + e0));
        atomicAdd(&g_deg[r4.x], 1);
        atomicAdd(&g_deg[r4.y], 1);
        atomicAdd(&g_deg[r4.z], 1);
        atomicAdd(&g_deg[r4.w], 1);
    } else if (e0 < E) {
        for (int e = e0; e < E; e++) atomicAdd(&g_deg[__ldg(row + e)], 1);
    }
}

// ---------------------------------------------------------------------------
// Scan 1: warp-shuffle block scan of degrees + per-partition degree bins.
// Last finished block scans the 196 block sums AND both 256-entry bin sets.
// ---------------------------------------------------------------------------
__global__ void k_scan1()
{
    __shared__ int sw[32];
    __shared__ int sbuf[256];
    __shared__ int isLast;
    int i    = blockIdx.x * SCAN_BLK + threadIdx.x;
    int lane = threadIdx.x & 31;
    int wid  = threadIdx.x >> 5;

    int v = (i < N_CNT) ? g_deg[i] : 0;

    int x = v;
    #pragma unroll
    for (int off = 1; off < 32; off <<= 1) {
        int y = __shfl_up_sync(0xffffffffu, x, off);
        if (lane >= off) x += y;
    }
    if (lane == 31) sw[wid] = x;
    __syncthreads();

    if (wid == 0) {
        int wv = sw[lane];
        int wx = wv;
        #pragma unroll
        for (int off = 1; off < 32; off <<= 1) {
            int y = __shfl_up_sync(0xffffffffu, wx, off);
            if (lane >= off) wx += y;
        }
        sw[lane] = wx - wv;
    }
    __syncthreads();

    int incl = x + sw[wid];
    if (i < N_CNT) g_ptr[i] = incl - v;             // exclusive, block-local
    if (threadIdx.x == SCAN_BLK - 1) g_bsum[blockIdx.x] = incl;

    if (i < N_CNT) {
        int d = v < DBINS ? v : DBINS - 1;
        atomicAdd(&g_dbin[i < U_CNT ? 0 : 1][d], 1);
    }

    __threadfence();
    if (threadIdx.x == 0)
        isLast = (atomicAdd(&g_tick, 1) == (int)gridDim.x - 1);
    __syncthreads();
    if (!isLast) return;

    int t = threadIdx.x;

    int v2 = (t < SCAN_NB) ? g_bsum[t] : 0;
    if (t < 256) sbuf[t] = v2;
    __syncthreads();
    for (int off = 1; off < 256; off <<= 1) {
        int u = (t < 256 && t >= off) ? sbuf[t - off] : 0;
        __syncthreads();
        if (t < 256) sbuf[t] += u;
        __syncthreads();
    }
    if (t < SCAN_NB) g_bsum[t] = sbuf[t] - v2;
    if (t == SCAN_NB - 1) g_ptr[N_CNT] = sbuf[t];
    __syncthreads();

    #pragma unroll
    for (int part = 0; part < 2; part++) {
        int v3 = (t < DBINS) ? g_dbin[part][t] : 0;
        if (t < 256) sbuf[t] = v3;
        __syncthreads();
        for (int off = 1; off < 256; off <<= 1) {
            int u = (t < 256 && t >= off) ? sbuf[t - off] : 0;
            __syncthreads();
            if (t < 256) sbuf[t] += u;
            __syncthreads();
        }
        if (t < DBINS) g_dbin[part][t] = sbuf[t] - v3;
        __syncthreads();
    }

    if (t == 0) g_tick = 0;   // restore invariant
}

// ---------------------------------------------------------------------------
// Scan 3: finalize ptr/cursor; per-partition descending-degree counting sort
// (users -> g_order[0,U), items -> g_order[U,N)). Re-zero g_deg (invariant).
// ---------------------------------------------------------------------------
__global__ void k_scan3()
{
    int i = blockIdx.x * blockDim.x + threadIdx.x;
    if (i >= N_CNT) return;
    int p = g_ptr[i] + g_bsum[i / SCAN_BLK];
    g_ptr[i]    = p;
    g_cursor[i] = p;
    int d = g_deg[i];
    d = d < DBINS ? d : DBINS - 1;
    if (i < U_CNT) {
        int pos = atomicAdd(&g_dbin[0][d], 1);
        g_order[U_CNT - 1 - pos] = i;
    } else {
        int pos = atomicAdd(&g_dbin[1][d], 1);
        g_order[U_CNT + I_CNT - 1 - pos] = i;
    }
    g_deg[i] = 0;             // restore invariant
}

// ---------------------------------------------------------------------------
// FUSED user-edge scatter + init (layer-0 mix + fp16 sem table in the shadow
// of the atomic round-trips). Re-zeroes BOTH g_dbin partitions.
// ---------------------------------------------------------------------------
__global__ void k_scatU_init(const int*    __restrict__ row, const int* __restrict__ col,
                             const float*  __restrict__ val, int E,
                             const float4* __restrict__ ue, const float4* __restrict__ ie,
                             const float4* __restrict__ se, const float4* __restrict__ he,
                             const float*  __restrict__ ulw, const float* __restrict__ ilw)
{
    int i = blockIdx.x * blockDim.x + threadIdx.x;
    if (blockIdx.x == 0 && threadIdx.x < DBINS) {
        ((int*)g_dbin)[threadIdx.x]         = 0;   // user bins
        ((int*)g_dbin)[threadIdx.x + DBINS] = 0;   // item bins
    }

    int e0 = i * 4;
    bool full = (e0 + 3 < E);
    int p[4], c[4];
    float v[4];
    bool m[4];
    if (full) {
        int4   r4 = __ldg((const int4*)(row + e0));
        int4   c4 = __ldg((const int4*)(col + e0));
        float4 v4 = __ldg((const float4*)(val + e0));
        int r[4] = { r4.x, r4.y, r4.z, r4.w };
        c[0] = c4.x; c[1] = c4.y; c[2] = c4.z; c[3] = c4.w;
        v[0] = v4.x; v[1] = v4.y; v[2] = v4.z; v[3] = v4.w;
        #pragma unroll
        for (int k = 0; k < 4; k++) {
            m[k] = (r[k] < U_CNT);
            p[k] = m[k] ? atomicAdd(&g_cursor[r[k]], 1) : 0;
        }
    }

    if (i < NH4) {
        int rw  = i >> 3;
        int sub = i & 7;

        const float4* base;
        const float4* sem;
        int r;
        float a;
        if (rw < U_CNT) { a = sigm(__ldg(ulw)); base = ue; sem = se; r = rw; }
        else            { a = sigm(__ldg(ilw)); base = ie; sem = he; r = rw - U_CNT; }

        float4 b0 = __ldcs(&base[r * ROW_F4 + sub * 2]);
        float4 b1 = __ldcs(&base[r * ROW_F4 + sub * 2 + 1]);
        float4 s0 = __ldcs(&sem [r * ROW_F4 + sub * 2]);
        float4 s1 = __ldcs(&sem [r * ROW_F4 + sub * 2 + 1]);

        float xs[8] = { s0.x, s0.y, s0.z, s0.w, s1.x, s1.y, s1.z, s1.w };
        float xb[8] = { b0.x, b0.y, b0.z, b0.w, b1.x, b1.y, b1.z, b1.w };
        float x[8];
        #pragma unroll
        for (int k = 0; k < 8; k++) x[k] = a * xb[k] + (1.0f - a) * xs[k];

        g_sem[i]   = pack8(xs);
        g_Lh[0][i] = pack8(x);
    }

    if (full) {
        #pragma unroll
        for (int k = 0; k < 4; k++) {
            if (m[k]) {
                int q = __float2int_rn(v[k] * VAL_ENC_SCALE);
                q = q < 16383 ? q : 16383;
                __stcs(&g_csr[p[k]], (unsigned)c[k] | ((unsigned)q << 18));
            }
        }
    } else if (e0 < E) {
        for (int e = e0; e < E; e++) {
            int r = __ldg(row + e);
            if (r >= U_CNT) continue;
            int pp = atomicAdd(&g_cursor[r], 1);
            int q = __float2int_rn(__ldg(val + e) * VAL_ENC_SCALE);
            q = q < 16383 ? q : 16383;
            __stcs(&g_csr[pp], (unsigned)__ldg(col + e) | ((unsigned)q << 18));
        }
    }
}

// ---------------------------------------------------------------------------
// FUSED: spmm layer-1 over USER rows  ∥  scatter of ITEM edges.
// Role by bid: bid%3==0 && bid/3 < SPMM_U_BLOCKS -> spmm; else scatter with
// sb = bid - min(ceil(bid/3), SPMM_U_BLOCKS).
// ---------------------------------------------------------------------------
__global__ void k_spmmU1_scatI(const int*   __restrict__ row, const int* __restrict__ col,
                               const float* __restrict__ val, int E,
                               const float* __restrict__ ulw, const float* __restrict__ ilw)
{
    int bid = blockIdx.x;
    bool is_spmm = (bid % 3 == 0) && (bid / 3 < SPMM_U_BLOCKS);
    if (is_spmm) {
        int t = (bid / 3) * blockDim.x + threadIdx.x;
        int g = t >> 3;
        if (g >= U_CNT) return;
        int sub = t & 7;
        int rw = __ldg(&g_order[g]);
        spmm_row_do(1, rw, sub, ulw, ilw);
        return;
    }
    int nsp = (bid + 2) / 3;
    if (nsp > SPMM_U_BLOCKS) nsp = SPMM_U_BLOCKS;
    int sb = bid - nsp;
    int i = sb * blockDim.x + threadIdx.x;

    int e0 = i * 4;
    if (e0 >= E) return;
    if (e0 + 3 < E) {
        int4   r4 = __ldg((const int4*)(row + e0));
        int4   c4 = __ldg((const int4*)(col + e0));
        float4 v4 = __ldg((const float4*)(val + e0));
        int r[4] = { r4.x, r4.y, r4.z, r4.w };
        int c[4] = { c4.x, c4.y, c4.z, c4.w };
        float v[4] = { v4.x, v4.y, v4.z, v4.w };
        int p[4];
        bool m[4];
        #pragma unroll
        for (int k = 0; k < 4; k++) {
            m[k] = (r[k] >= U_CNT);
            p[k] = m[k] ? atomicAdd(&g_cursor[r[k]], 1) : 0;
        }
        #pragma unroll
        for (int k = 0; k < 4; k++) {
            if (m[k]) {
                int q = __float2int_rn(v[k] * VAL_ENC_SCALE);
                q = q < 16383 ? q : 16383;
                __stcs(&g_csr[p[k]], (unsigned)c[k] | ((unsigned)q << 18));
            }
        }
    } else {
        for (int e = e0; e < E; e++) {
            int r = __ldg(row + e);
            if (r < U_CNT) continue;
            int pp = atomicAdd(&g_cursor[r], 1);
            int q = __float2int_rn(__ldg(val + e) * VAL_ENC_SCALE);
            q = q < 16383 ? q : 16383;
            __stcs(&g_csr[pp], (unsigned)__ldg(col + e) | ((unsigned)q << 18));
        }
    }
}

// ---------------------------------------------------------------------------
// SpMM layer-1 over ITEM rows only.
// ---------------------------------------------------------------------------
__global__ void k_spmmI1(const float* __restrict__ ulw, const float* __restrict__ ilw)
{
    int t = blockIdx.x * blockDim.x + threadIdx.x;
    int g = t >> 3;
    if (g >= I_CNT) return;
    int sub = t & 7;
    int rw = __ldg(&g_order[U_CNT + g]);
    spmm_row_do(1, rw, sub, ulw, ilw);
}

// ---------------------------------------------------------------------------
// Full SpMM (layer 2) over all rows.
// ---------------------------------------------------------------------------
__global__ void k_spmm_fused(const float* __restrict__ ulw, const float* __restrict__ ilw,
                             int layer)
{
    int t = blockIdx.x * blockDim.x + threadIdx.x;
    int g = t >> 3;
    if (g >= N_CNT) return;
    int sub = t & 7;
    int rw = __ldg(&g_order[g]);
    spmm_row_do(layer, rw, sub, ulw, ilw);
}

// ---------------------------------------------------------------------------
// FUSED dot + on-demand layer 3: for each (user, item) pair, compute the
// layer-3 value of both rows directly from g_Lh[2] via the CSR gather loop
// (fp32, never stored), add layers 0..2 from the fp16 buffers, dot, reduce.
// No layer-3 buffer, no selection state, no invariants.
// ---------------------------------------------------------------------------
__device__ __forceinline__ void row_sum_with_l3(int rw, int sub, float a3,
                                                float* s)
{
    // layer-3 gather from g_Lh[2]
    float acc[8];
    #pragma unroll
    for (int k = 0; k < 8; k++) acc[k] = 0.0f;
    gather_row(g_Lh[2], rw, sub, acc);

    float o[8];
    unpack8(__ldg(&g_sem[rw * ROW_H4 + sub]), o);

    // s = L3 + L0 + L1 + L2
    #pragma unroll
    for (int k = 0; k < 8; k++) s[k] = a3 * acc[k] + (1.0f - a3) * o[k];

    #pragma unroll
    for (int l = 0; l < 3; l++) {
        float x[8];
        unpack8(__ldg(&g_Lh[l][rw * ROW_H4 + sub]), x);
        #pragma unroll
        for (int k = 0; k < 8; k++) s[k] += x[k];
    }
}

__global__ void k_dot3(const int* __restrict__ users, const int* __restrict__ items,
                       const float* __restrict__ ulw, const float* __restrict__ ilw,
                       float* __restrict__ out, int B)
{
    int t = blockIdx.x * blockDim.x + threadIdx.x;
    int b = t >> 3;
    if (b >= B) return;
    int sub = t & 7;

    int u  = __ldg(users + b);
    int it = __ldg(items + b) + U_CNT;

    float aU = sigm(__ldg(ulw + L_LAYERS));
    float aI = sigm(__ldg(ilw + L_LAYERS));

    float su[8], si[8];
    row_sum_with_l3(u,  sub, aU, su);
    row_sum_with_l3(it, sub, aI, si);

    float s = 0.0f;
    #pragma unroll
    for (int k = 0; k < 8; k++) s = fmaf(su[k], si[k], s);

    s += __shfl_down_sync(0xffffffffu, s, 4, 8);
    s += __shfl_down_sync(0xffffffffu, s, 2, 8);
    s += __shfl_down_sync(0xffffffffu, s, 1, 8);

    if (sub == 0) out[b] = s * (1.0f / ((L_LAYERS + 1) * (L_LAYERS + 1)));
}

// ---------------------------------------------------------------------------
// Launch sequence: hist | scan1 | scan3 | scatU+init | spmmU1∥scatI |
// spmmI1 | spmm2 | dot3.   (8 launches)
// ---------------------------------------------------------------------------
extern "C" void kernel_launch(void* const* d_in, const int* in_sizes, int n_in,
                              void* d_out, int out_size)
{
    const float4* user_emb    = (const float4*)d_in[0];
    const float4* item_emb    = (const float4*)d_in[1];
    const float4* symptom_emb = (const float4*)d_in[2];
    const float4* herb_emb    = (const float4*)d_in[3];
    const float*  user_lw     = (const float*)d_in[4];
    const float*  item_lw     = (const float*)d_in[5];
    const float*  edge_val    = (const float*)d_in[6];
    const int*    edge_row    = (const int*)d_in[7];
    const int*    edge_col    = (const int*)d_in[8];
    const int*    users       = (const int*)d_in[9];
    const int*    items       = (const int*)d_in[10];

    int E = in_sizes[6];
    int B = in_sizes[9];

    const int TB = 256;
    int e4 = (E + 3) / 4;

    k_hist<<<(e4 + TB - 1) / TB, TB>>>(edge_row, E);
    k_scan1<<<SCAN_NB, SCAN_BLK>>>();
    k_scan3<<<(N_CNT + TB - 1) / TB, TB>>>();

    int si_threads = (e4 > NH4 ? e4 : NH4);
    k_scatU_init<<<(si_threads + TB - 1) / TB, TB>>>(
        edge_row, edge_col, edge_val, E,
        user_emb, item_emb, symptom_emb, herb_emb, user_lw, item_lw);

    int scat_blocks = (e4 + TB - 1) / TB;
    int k5_blocks = SPMM_U_BLOCKS + scat_blocks;
    int need_for_spmm = (SPMM_U_BLOCKS - 1) * 3 + 1;
    if (k5_blocks < need_for_spmm) k5_blocks = need_for_spmm;
    k_spmmU1_scatI<<<k5_blocks, TB>>>(edge_row, edge_col, edge_val, E,
                                      user_lw, item_lw);

    k_spmmI1<<<(I_CNT * 8 + TB - 1) / TB, TB>>>(user_lw, item_lw);

    k_spmm_fused<<<(N_CNT * 8 + TB - 1) / TB, TB>>>(user_lw, item_lw, 2);

    k_dot3<<<(B * 8 + TB - 1) / TB, TB>>>(users, items, user_lw, item_lw,
                                          (float*)d_out, B);
}

// round 14
// speedup vs baseline: 1.3058x; 1.0017x over previous
#include <cuda_runtime.h>
#include <cuda_fp16.h>
#include <cuda_bf16.h>

// Problem constants (fixed by the reference).
#define U_CNT 100000
#define I_CNT 100000
#define N_CNT 200000           // U + I
#define L_LAYERS 3
#define ROW_F4 16              // D/4 float4 per node row (fp32 inputs)
#define ROW_H4 8               // 8 uint4 per node row (64 halves, 128B)
#define NH4   (N_CNT * ROW_H4) // 1.6M uint4 = 25.6 MB per layer buffer
#define E_MAX 6400000
#define SCAN_BLK 1024
#define SCAN_NB ((N_CNT + SCAN_BLK - 1) / SCAN_BLK)   // 196
#define DBINS 256
#define SPMM_U_BLOCKS ((U_CNT * 8 + 255) / 256)       // 3125

// val quantization: val in [0, 1/32), 14-bit fixed point in bits [18,32).
#define VAL_ENC_SCALE (32.0f * 16383.0f)
#define VAL_DEC_SCALE (1.0f / (32.0f * 16383.0f))

// Scratch (__device__ globals only — allocation-free rule).
// Steady-state invariants maintained across calls (zero-init by loader first):
//   g_deg  == 0 on entry (re-zeroed in k_scan3)
//   g_dbin == 0 on entry (re-zeroed in k_scatU_init — BOTH partitions)
//   g_tick == 0 on entry (re-zeroed by scan1's last block)
__device__ uint4    g_Lh[L_LAYERS][NH4];       // fp16 layer buffers 0..2
__device__ uint4    g_sem[NH4];                // fp16 semantic (symptom|herb) table
__device__ unsigned g_csr [E_MAX];             // packed (col | q<<18), grouped by row
__device__ int      g_deg [N_CNT];
__device__ int      g_ptr [N_CNT + 1];
__device__ int      g_cursor[N_CNT];
__device__ int      g_bsum[SCAN_NB];
__device__ int      g_dbin[2][DBINS];          // degree bins: [0]=users, [1]=items
__device__ int      g_order[N_CNT];            // users desc-deg in [0,U), items in [U,N)
__device__ int      g_tick;

__device__ __forceinline__ float sigm(float x) { return 1.0f / (1.0f + __expf(-x)); }

__device__ __forceinline__ uint4 pack8(const float* x)
{
    uint4 r;
    half2 h0 = __floats2half2_rn(x[0], x[1]);
    half2 h1 = __floats2half2_rn(x[2], x[3]);
    half2 h2 = __floats2half2_rn(x[4], x[5]);
    half2 h3 = __floats2half2_rn(x[6], x[7]);
    r.x = *(unsigned*)&h0; r.y = *(unsigned*)&h1;
    r.z = *(unsigned*)&h2; r.w = *(unsigned*)&h3;
    return r;
}

__device__ __forceinline__ void unpack8(uint4 q, float* x)
{
    half2* hp = (half2*)&q;
    float2 f0 = __half22float2(hp[0]);
    float2 f1 = __half22float2(hp[1]);
    float2 f2 = __half22float2(hp[2]);
    float2 f3 = __half22float2(hp[3]);
    x[0] = f0.x; x[1] = f0.y; x[2] = f1.x; x[3] = f1.y;
    x[4] = f2.x; x[5] = f2.y; x[6] = f3.x; x[7] = f3.y;
}

__device__ __forceinline__ void acc8(float* acc, uint4 q, float v)
{
    float x[8];
    unpack8(q, x);
    #pragma unroll
    for (int k = 0; k < 8; k++) acc[k] = fmaf(v, x[k], acc[k]);
}

// CSR gather-accumulate over src for row rw: acc += sum(val * src[col]).
__device__ __forceinline__ void gather_row(const uint4* __restrict__ src,
                                           int rw, int sub, float* acc)
{
    int start = __ldg(&g_ptr[rw]);
    int end   = __ldg(&g_ptr[rw + 1]);
    int j = start;
    for (; j + 4 <= end; j += 4) {
        unsigned e0 = __ldg(&g_csr[j + 0]);
        unsigned e1 = __ldg(&g_csr[j + 1]);
        unsigned e2 = __ldg(&g_csr[j + 2]);
        unsigned e3 = __ldg(&g_csr[j + 3]);
        uint4 q0 = __ldg(&src[(e0 & 0x3FFFFu) * ROW_H4 + sub]);
        uint4 q1 = __ldg(&src[(e1 & 0x3FFFFu) * ROW_H4 + sub]);
        uint4 q2 = __ldg(&src[(e2 & 0x3FFFFu) * ROW_H4 + sub]);
        uint4 q3 = __ldg(&src[(e3 & 0x3FFFFu) * ROW_H4 + sub]);
        acc8(acc, q0, (float)(e0 >> 18) * VAL_DEC_SCALE);
        acc8(acc, q1, (float)(e1 >> 18) * VAL_DEC_SCALE);
        acc8(acc, q2, (float)(e2 >> 18) * VAL_DEC_SCALE);
        acc8(acc, q3, (float)(e3 >> 18) * VAL_DEC_SCALE);
    }
    for (; j < end; j++) {
        unsigned e0 = __ldg(&g_csr[j]);
        uint4 q0 = __ldg(&src[(e0 & 0x3FFFFu) * ROW_H4 + sub]);
        acc8(acc, q0, (float)(e0 >> 18) * VAL_DEC_SCALE);
    }
}

// Shared SpMM row body: gather+accumulate row `rw` of `layer`, mix, store.
// Plain store for dst: it is the NEXT layer's random-gather source — keep in L2.
__device__ __forceinline__ void spmm_row_do(int layer, int rw, int sub,
                                            const float* __restrict__ ulw,
                                            const float* __restrict__ ilw)
{
    const uint4* __restrict__ src = g_Lh[layer - 1];
    uint4*       __restrict__ dst = g_Lh[layer];

    float acc[8];
    #pragma unroll
    for (int k = 0; k < 8; k++) acc[k] = 0.0f;
    gather_row(src, rw, sub, acc);

    float a = (rw < U_CNT) ? sigm(__ldg(ulw + layer)) : sigm(__ldg(ilw + layer));

    float o[8];
    unpack8(__ldg(&g_sem[rw * ROW_H4 + sub]), o);

    float x[8];
    #pragma unroll
    for (int k = 0; k < 8; k++) x[k] = a * acc[k] + (1.0f - a) * o[k];

    dst[rw * ROW_H4 + sub] = pack8(x);
}

// ---------------------------------------------------------------------------
// Degree histogram: fire-and-forget REDG atomics, 4 edges/thread.
// ---------------------------------------------------------------------------
__global__ void k_hist(const int* __restrict__ row, int E)
{
    int i = blockIdx.x * blockDim.x + threadIdx.x;
    int e0 = i * 4;
    if (e0 + 3 < E) {
        int4 r4 = __ldg((const int4*)(row + e0));
        atomicAdd(&g_deg[r4.x], 1);
        atomicAdd(&g_deg[r4.y], 1);
        atomicAdd(&g_deg[r4.z], 1);
        atomicAdd(&g_deg[r4.w], 1);
    } else if (e0 < E) {
        for (int e = e0; e < E; e++) atomicAdd(&g_deg[__ldg(row + e)], 1);
    }
}

// ---------------------------------------------------------------------------
// Scan 1: warp-shuffle block scan of degrees + per-partition degree bins.
// Last finished block scans the 196 block sums AND both 256-entry bin sets.
// ---------------------------------------------------------------------------
__global__ void k_scan1()
{
    __shared__ int sw[32];
    __shared__ int sbuf[256];
    __shared__ int isLast;
    int i    = blockIdx.x * SCAN_BLK + threadIdx.x;
    int lane = threadIdx.x & 31;
    int wid  = threadIdx.x >> 5;

    int v = (i < N_CNT) ? g_deg[i] : 0;

    int x = v;
    #pragma unroll
    for (int off = 1; off < 32; off <<= 1) {
        int y = __shfl_up_sync(0xffffffffu, x, off);
        if (lane >= off) x += y;
    }
    if (lane == 31) sw[wid] = x;
    __syncthreads();

    if (wid == 0) {
        int wv = sw[lane];
        int wx = wv;
        #pragma unroll
        for (int off = 1; off < 32; off <<= 1) {
            int y = __shfl_up_sync(0xffffffffu, wx, off);
            if (lane >= off) wx += y;
        }
        sw[lane] = wx - wv;
    }
    __syncthreads();

    int incl = x + sw[wid];
    if (i < N_CNT) g_ptr[i] = incl - v;             // exclusive, block-local
    if (threadIdx.x == SCAN_BLK - 1) g_bsum[blockIdx.x] = incl;

    if (i < N_CNT) {
        int d = v < DBINS ? v : DBINS - 1;
        atomicAdd(&g_dbin[i < U_CNT ? 0 : 1][d], 1);
    }

    __threadfence();
    if (threadIdx.x == 0)
        isLast = (atomicAdd(&g_tick, 1) == (int)gridDim.x - 1);
    __syncthreads();
    if (!isLast) return;

    int t = threadIdx.x;

    int v2 = (t < SCAN_NB) ? g_bsum[t] : 0;
    if (t < 256) sbuf[t] = v2;
    __syncthreads();
    for (int off = 1; off < 256; off <<= 1) {
        int u = (t < 256 && t >= off) ? sbuf[t - off] : 0;
        __syncthreads();
        if (t < 256) sbuf[t] += u;
        __syncthreads();
    }
    if (t < SCAN_NB) g_bsum[t] = sbuf[t] - v2;
    if (t == SCAN_NB - 1) g_ptr[N_CNT] = sbuf[t];
    __syncthreads();

    #pragma unroll
    for (int part = 0; part < 2; part++) {
        int v3 = (t < DBINS) ? g_dbin[part][t] : 0;
        if (t < 256) sbuf[t] = v3;
        __syncthreads();
        for (int off = 1; off < 256; off <<= 1) {
            int u = (t < 256 && t >= off) ? sbuf[t - off] : 0;
            __syncthreads();
            if (t < 256) sbuf[t] += u;
            __syncthreads();
        }
        if (t < DBINS) g_dbin[part][t] = sbuf[t] - v3;
        __syncthreads();
    }

    if (t == 0) g_tick = 0;   // restore invariant
}

// ---------------------------------------------------------------------------
// Scan 3: finalize ptr/cursor; per-partition descending-degree counting sort
// (users -> g_order[0,U), items -> g_order[U,N)). Re-zero g_deg (invariant).
// ---------------------------------------------------------------------------
__global__ void k_scan3()
{
    int i = blockIdx.x * blockDim.x + threadIdx.x;
    if (i >= N_CNT) return;
    int p = g_ptr[i] + g_bsum[i / SCAN_BLK];
    g_ptr[i]    = p;
    g_cursor[i] = p;
    int d = g_deg[i];
    d = d < DBINS ? d : DBINS - 1;
    if (i < U_CNT) {
        int pos = atomicAdd(&g_dbin[0][d], 1);
        g_order[U_CNT - 1 - pos] = i;
    } else {
        int pos = atomicAdd(&g_dbin[1][d], 1);
        g_order[U_CNT + I_CNT - 1 - pos] = i;
    }
    g_deg[i] = 0;             // restore invariant
}

// ---------------------------------------------------------------------------
// FUSED user-edge scatter + init (layer-0 mix + fp16 sem table in the shadow
// of the atomic round-trips). Re-zeroes BOTH g_dbin partitions.
// CSR stores are PLAIN (re-read 3x: layer1, layer2, dot3 — keep in L2).
// ---------------------------------------------------------------------------
__global__ void k_scatU_init(const int*    __restrict__ row, const int* __restrict__ col,
                             const float*  __restrict__ val, int E,
                             const float4* __restrict__ ue, const float4* __restrict__ ie,
                             const float4* __restrict__ se, const float4* __restrict__ he,
                             const float*  __restrict__ ulw, const float* __restrict__ ilw)
{
    int i = blockIdx.x * blockDim.x + threadIdx.x;
    if (blockIdx.x == 0 && threadIdx.x < DBINS) {
        ((int*)g_dbin)[threadIdx.x]         = 0;   // user bins
        ((int*)g_dbin)[threadIdx.x + DBINS] = 0;   // item bins
    }

    int e0 = i * 4;
    bool full = (e0 + 3 < E);
    int p[4], c[4];
    float v[4];
    bool m[4];
    if (full) {
        int4   r4 = __ldg((const int4*)(row + e0));
        int4   c4 = __ldg((const int4*)(col + e0));
        float4 v4 = __ldg((const float4*)(val + e0));
        int r[4] = { r4.x, r4.y, r4.z, r4.w };
        c[0] = c4.x; c[1] = c4.y; c[2] = c4.z; c[3] = c4.w;
        v[0] = v4.x; v[1] = v4.y; v[2] = v4.z; v[3] = v4.w;
        #pragma unroll
        for (int k = 0; k < 4; k++) {
            m[k] = (r[k] < U_CNT);
            p[k] = m[k] ? atomicAdd(&g_cursor[r[k]], 1) : 0;
        }
    }

    if (i < NH4) {
        int rw  = i >> 3;
        int sub = i & 7;

        const float4* base;
        const float4* sem;
        int r;
        float a;
        if (rw < U_CNT) { a = sigm(__ldg(ulw)); base = ue; sem = se; r = rw; }
        else            { a = sigm(__ldg(ilw)); base = ie; sem = he; r = rw - U_CNT; }

        float4 b0 = __ldcs(&base[r * ROW_F4 + sub * 2]);
        float4 b1 = __ldcs(&base[r * ROW_F4 + sub * 2 + 1]);
        float4 s0 = __ldcs(&sem [r * ROW_F4 + sub * 2]);
        float4 s1 = __ldcs(&sem [r * ROW_F4 + sub * 2 + 1]);

        float xs[8] = { s0.x, s0.y, s0.z, s0.w, s1.x, s1.y, s1.z, s1.w };
        float xb[8] = { b0.x, b0.y, b0.z, b0.w, b1.x, b1.y, b1.z, b1.w };
        float x[8];
        #pragma unroll
        for (int k = 0; k < 8; k++) x[k] = a * xb[k] + (1.0f - a) * xs[k];

        g_sem[i]   = pack8(xs);
        g_Lh[0][i] = pack8(x);
    }

    if (full) {
        #pragma unroll
        for (int k = 0; k < 4; k++) {
            if (m[k]) {
                int q = __float2int_rn(v[k] * VAL_ENC_SCALE);
                q = q < 16383 ? q : 16383;
                g_csr[p[k]] = (unsigned)c[k] | ((unsigned)q << 18);
            }
        }
    } else if (e0 < E) {
        for (int e = e0; e < E; e++) {
            int r = __ldg(row + e);
            if (r >= U_CNT) continue;
            int pp = atomicAdd(&g_cursor[r], 1);
            int q = __float2int_rn(__ldg(val + e) * VAL_ENC_SCALE);
            q = q < 16383 ? q : 16383;
            g_csr[pp] = (unsigned)__ldg(col + e) | ((unsigned)q << 18);
        }
    }
}

// ---------------------------------------------------------------------------
// FUSED: spmm layer-1 over USER rows  ∥  scatter of ITEM edges.
// Role by bid: bid%3==0 && bid/3 < SPMM_U_BLOCKS -> spmm; else scatter with
// sb = bid - min(ceil(bid/3), SPMM_U_BLOCKS).
// ---------------------------------------------------------------------------
__global__ void k_spmmU1_scatI(const int*   __restrict__ row, const int* __restrict__ col,
                               const float* __restrict__ val, int E,
                               const float* __restrict__ ulw, const float* __restrict__ ilw)
{
    int bid = blockIdx.x;
    bool is_spmm = (bid % 3 == 0) && (bid / 3 < SPMM_U_BLOCKS);
    if (is_spmm) {
        int t = (bid / 3) * blockDim.x + threadIdx.x;
        int g = t >> 3;
        if (g >= U_CNT) return;
        int sub = t & 7;
        int rw = __ldg(&g_order[g]);
        spmm_row_do(1, rw, sub, ulw, ilw);
        return;
    }
    int nsp = (bid + 2) / 3;
    if (nsp > SPMM_U_BLOCKS) nsp = SPMM_U_BLOCKS;
    int sb = bid - nsp;
    int i = sb * blockDim.x + threadIdx.x;

    int e0 = i * 4;
    if (e0 >= E) return;
    if (e0 + 3 < E) {
        int4   r4 = __ldg((const int4*)(row + e0));
        int4   c4 = __ldg((const int4*)(col + e0));
        float4 v4 = __ldg((const float4*)(val + e0));
        int r[4] = { r4.x, r4.y, r4.z, r4.w };
        int c[4] = { c4.x, c4.y, c4.z, c4.w };
        float v[4] = { v4.x, v4.y, v4.z, v4.w };
        int p[4];
        bool m[4];
        #pragma unroll
        for (int k = 0; k < 4; k++) {
            m[k] = (r[k] >= U_CNT);
            p[k] = m[k] ? atomicAdd(&g_cursor[r[k]], 1) : 0;
        }
        #pragma unroll
        for (int k = 0; k < 4; k++) {
            if (m[k]) {
                int q = __float2int_rn(v[k] * VAL_ENC_SCALE);
                q = q < 16383 ? q : 16383;
                g_csr[p[k]] = (unsigned)c[k] | ((unsigned)q << 18);
            }
        }
    } else {
        for (int e = e0; e < E; e++) {
            int r = __ldg(row + e);
            if (r < U_CNT) continue;
            int pp = atomicAdd(&g_cursor[r], 1);
            int q = __float2int_rn(__ldg(val + e) * VAL_ENC_SCALE);
            q = q < 16383 ? q : 16383;
            g_csr[pp] = (unsigned)__ldg(col + e) | ((unsigned)q << 18);
        }
    }
}

// ---------------------------------------------------------------------------
// SpMM layer-1 over ITEM rows only.
// ---------------------------------------------------------------------------
__global__ void k_spmmI1(const float* __restrict__ ulw, const float* __restrict__ ilw)
{
    int t = blockIdx.x * blockDim.x + threadIdx.x;
    int g = t >> 3;
    if (g >= I_CNT) return;
    int sub = t & 7;
    int rw = __ldg(&g_order[U_CNT + g]);
    spmm_row_do(1, rw, sub, ulw, ilw);
}

// ---------------------------------------------------------------------------
// Full SpMM (layer 2) over all rows.
// ---------------------------------------------------------------------------
__global__ void k_spmm_fused(const float* __restrict__ ulw, const float* __restrict__ ilw,
                             int layer)
{
    int t = blockIdx.x * blockDim.x + threadIdx.x;
    int g = t >> 3;
    if (g >= N_CNT) return;
    int sub = t & 7;
    int rw = __ldg(&g_order[g]);
    spmm_row_do(layer, rw, sub, ulw, ilw);
}

// ---------------------------------------------------------------------------
// FUSED dot + on-demand layer 3 (fp32, never stored).
// ---------------------------------------------------------------------------
__device__ __forceinline__ void row_sum_with_l3(int rw, int sub, float a3,
                                                float* s)
{
    float acc[8];
    #pragma unroll
    for (int k = 0; k < 8; k++) acc[k] = 0.0f;
    gather_row(g_Lh[2], rw, sub, acc);

    float o[8];
    unpack8(__ldg(&g_sem[rw * ROW_H4 + sub]), o);

    #pragma unroll
    for (int k = 0; k < 8; k++) s[k] = a3 * acc[k] + (1.0f - a3) * o[k];

    #pragma unroll
    for (int l = 0; l < 3; l++) {
        float x[8];
        unpack8(__ldg(&g_Lh[l][rw * ROW_H4 + sub]), x);
        #pragma unroll
        for (int k = 0; k < 8; k++) s[k] += x[k];
    }
}

__global__ void k_dot3(const int* __restrict__ users, const int* __restrict__ items,
                       const float* __restrict__ ulw, const float* __restrict__ ilw,
                       float* __restrict__ out, int B)
{
    int t = blockIdx.x * blockDim.x + threadIdx.x;
    int b = t >> 3;
    if (b >= B) return;
    int sub = t & 7;

    int u  = __ldg(users + b);
    int it = __ldg(items + b) + U_CNT;

    float aU = sigm(__ldg(ulw + L_LAYERS));
    float aI = sigm(__ldg(ilw + L_LAYERS));

    float su[8], si[8];
    row_sum_with_l3(u,  sub, aU, su);
    row_sum_with_l3(it, sub, aI, si);

    float s = 0.0f;
    #pragma unroll
    for (int k = 0; k < 8; k++) s = fmaf(su[k], si[k], s);

    s += __shfl_down_sync(0xffffffffu, s, 4, 8);
    s += __shfl_down_sync(0xffffffffu, s, 2, 8);
    s += __shfl_down_sync(0xffffffffu, s, 1, 8);

    if (sub == 0) out[b] = s * (1.0f / ((L_LAYERS + 1) * (L_LAYERS + 1)));
}

// ---------------------------------------------------------------------------
// Launch sequence: hist | scan1 | scan3 | scatU+init | spmmU1∥scatI |
// spmmI1 | spmm2 | dot3.   (8 launches)
// ---------------------------------------------------------------------------
extern "C" void kernel_launch(void* const* d_in, const int* in_sizes, int n_in,
                              void* d_out, int out_size)
{
    const float4* user_emb    = (const float4*)d_in[0];
    const float4* item_emb    = (const float4*)d_in[1];
    const float4* symptom_emb = (const float4*)d_in[2];
    const float4* herb_emb    = (const float4*)d_in[3];
    const float*  user_lw     = (const float*)d_in[4];
    const float*  item_lw     = (const float*)d_in[5];
    const float*  edge_val    = (const float*)d_in[6];
    const int*    edge_row    = (const int*)d_in[7];
    const int*    edge_col    = (const int*)d_in[8];
    const int*    users       = (const int*)d_in[9];
    const int*    items       = (const int*)d_in[10];

    int E = in_sizes[6];
    int B = in_sizes[9];

    const int TB = 256;
    int e4 = (E + 3) / 4;

    k_hist<<<(e4 + TB - 1) / TB, TB>>>(edge_row, E);
    k_scan1<<<SCAN_NB, SCAN_BLK>>>();
    k_scan3<<<(N_CNT + TB - 1) / TB, TB>>>();

    int si_threads = (e4 > NH4 ? e4 : NH4);
    k_scatU_init<<<(si_threads + TB - 1) / TB, TB>>>(
        edge_row, edge_col, edge_val, E,
        user_emb, item_emb, symptom_emb, herb_emb, user_lw, item_lw);

    int scat_blocks = (e4 + TB - 1) / TB;
    int k5_blocks = SPMM_U_BLOCKS + scat_blocks;
    int need_for_spmm = (SPMM_U_BLOCKS - 1) * 3 + 1;
    if (k5_blocks < need_for_spmm) k5_blocks = need_for_spmm;
    k_spmmU1_scatI<<<k5_blocks, TB>>>(edge_row, edge_col, edge_val, E,
                                      user_lw, item_lw);

    k_spmmI1<<<(I_CNT * 8 + TB - 1) / TB, TB>>>(user_lw, item_lw);

    k_spmm_fused<<<(N_CNT * 8 + TB - 1) / TB, TB>>>(user_lw, item_lw, 2);

    k_dot3<<<(B * 8 + TB - 1) / TB, TB>>>(users, items, user_lw, item_lw,
                                          (float*)d_out, B);
}

// round 15
// speedup vs baseline: 1.3129x; 1.0054x over previous
#include <cuda_runtime.h>
#include <cuda_fp16.h>
#include <cuda_bf16.h>

// Problem constants (fixed by the reference).
#define U_CNT 100000
#define I_CNT 100000
#define N_CNT 200000           // U + I
#define L_LAYERS 3
#define ROW_F4 16              // D/4 float4 per node row (fp32 inputs)
#define ROW_H4 8               // 8 uint4 per node row (64 halves, 128B)
#define NH4   (N_CNT * ROW_H4) // 1.6M uint4 = 25.6 MB per layer buffer
#define E_MAX 6400000
#define SCAN_BLK 1024
#define SCAN_NB ((N_CNT + SCAN_BLK - 1) / SCAN_BLK)   // 196
#define DBINS 256
#define SPMM_U_BLOCKS ((U_CNT * 8 + 255) / 256)       // 3125

// val quantization: val in [0, 1/32), 14-bit fixed point in bits [18,32).
#define VAL_ENC_SCALE (32.0f * 16383.0f)
#define VAL_DEC_SCALE (1.0f / (32.0f * 16383.0f))

// Scratch (__device__ globals only — allocation-free rule).
// Steady-state invariants (zero-init by loader; restored every call):
//   g_deg   == 0 on entry (re-zeroed in k_scan13 phase C)
//   g_dbin  == 0 on entry (re-zeroed in k_scatU — BOTH partitions)
//   g_tick/g_tick2/g_rel == 0 on entry (self-resetting barrier in k_scan13)
__device__ uint4    g_Lh[L_LAYERS][NH4];       // fp16 layer buffers 0..2
__device__ uint4    g_sem[NH4];                // fp16 semantic (symptom|herb) table
__device__ unsigned g_csr [E_MAX];             // packed (col | q<<18), grouped by row
__device__ int      g_deg [N_CNT];
__device__ int      g_ptr [N_CNT + 1];
__device__ int      g_cursor[N_CNT];
__device__ int      g_bsum[SCAN_NB];
__device__ int      g_dbin[2][DBINS];          // degree bins: [0]=users, [1]=items
__device__ int      g_order[N_CNT];            // users desc-deg in [0,U), items in [U,N)
__device__ int      g_tick;                    // barrier arrive counter
__device__ int      g_tick2;                   // barrier depart counter
__device__ int      g_rel;                     // barrier release flag

__device__ __forceinline__ float sigm(float x) { return 1.0f / (1.0f + __expf(-x)); }

__device__ __forceinline__ uint4 pack8(const float* x)
{
    uint4 r;
    half2 h0 = __floats2half2_rn(x[0], x[1]);
    half2 h1 = __floats2half2_rn(x[2], x[3]);
    half2 h2 = __floats2half2_rn(x[4], x[5]);
    half2 h3 = __floats2half2_rn(x[6], x[7]);
    r.x = *(unsigned*)&h0; r.y = *(unsigned*)&h1;
    r.z = *(unsigned*)&h2; r.w = *(unsigned*)&h3;
    return r;
}

__device__ __forceinline__ void unpack8(uint4 q, float* x)
{
    half2* hp = (half2*)&q;
    float2 f0 = __half22float2(hp[0]);
    float2 f1 = __half22float2(hp[1]);
    float2 f2 = __half22float2(hp[2]);
    float2 f3 = __half22float2(hp[3]);
    x[0] = f0.x; x[1] = f0.y; x[2] = f1.x; x[3] = f1.y;
    x[4] = f2.x; x[5] = f2.y; x[6] = f3.x; x[7] = f3.y;
}

__device__ __forceinline__ void acc8(float* acc, uint4 q, float v)
{
    float x[8];
    unpack8(q, x);
    #pragma unroll
    for (int k = 0; k < 8; k++) acc[k] = fmaf(v, x[k], acc[k]);
}

// CSR gather-accumulate over src for row rw: acc += sum(val * src[col]).
__device__ __forceinline__ void gather_row(const uint4* __restrict__ src,
                                           int rw, int sub, float* acc)
{
    int start = __ldg(&g_ptr[rw]);
    int end   = __ldg(&g_ptr[rw + 1]);
    int j = start;
    for (; j + 4 <= end; j += 4) {
        unsigned e0 = __ldg(&g_csr[j + 0]);
        unsigned e1 = __ldg(&g_csr[j + 1]);
        unsigned e2 = __ldg(&g_csr[j + 2]);
        unsigned e3 = __ldg(&g_csr[j + 3]);
        uint4 q0 = __ldg(&src[(e0 & 0x3FFFFu) * ROW_H4 + sub]);
        uint4 q1 = __ldg(&src[(e1 & 0x3FFFFu) * ROW_H4 + sub]);
        uint4 q2 = __ldg(&src[(e2 & 0x3FFFFu) * ROW_H4 + sub]);
        uint4 q3 = __ldg(&src[(e3 & 0x3FFFFu) * ROW_H4 + sub]);
        acc8(acc, q0, (float)(e0 >> 18) * VAL_DEC_SCALE);
        acc8(acc, q1, (float)(e1 >> 18) * VAL_DEC_SCALE);
        acc8(acc, q2, (float)(e2 >> 18) * VAL_DEC_SCALE);
        acc8(acc, q3, (float)(e3 >> 18) * VAL_DEC_SCALE);
    }
    for (; j < end; j++) {
        unsigned e0 = __ldg(&g_csr[j]);
        uint4 q0 = __ldg(&src[(e0 & 0x3FFFFu) * ROW_H4 + sub]);
        acc8(acc, q0, (float)(e0 >> 18) * VAL_DEC_SCALE);
    }
}

// Shared SpMM row body: gather+accumulate row `rw` of `layer`, mix, store.
__device__ __forceinline__ void spmm_row_do(int layer, int rw, int sub,
                                            const float* __restrict__ ulw,
                                            const float* __restrict__ ilw)
{
    const uint4* __restrict__ src = g_Lh[layer - 1];
    uint4*       __restrict__ dst = g_Lh[layer];

    float acc[8];
    #pragma unroll
    for (int k = 0; k < 8; k++) acc[k] = 0.0f;
    gather_row(src, rw, sub, acc);

    float a = (rw < U_CNT) ? sigm(__ldg(ulw + layer)) : sigm(__ldg(ilw + layer));

    float o[8];
    unpack8(__ldg(&g_sem[rw * ROW_H4 + sub]), o);

    float x[8];
    #pragma unroll
    for (int k = 0; k < 8; k++) x[k] = a * acc[k] + (1.0f - a) * o[k];

    dst[rw * ROW_H4 + sub] = pack8(x);
}

// ---------------------------------------------------------------------------
// FUSED degree histogram (fire-and-forget REDG, 4 edges/thread) + init
// (layer-0 mix + fp16 sem table). Init's DRAM stream hides fully behind the
// LTS-atomic-bound histogram (R5-measured ≈35us for the pair).
// Requires g_deg == 0 on entry (invariant).
// ---------------------------------------------------------------------------
__global__ void k_hist_init(const int*    __restrict__ row, int E,
                            const float4* __restrict__ ue, const float4* __restrict__ ie,
                            const float4* __restrict__ se, const float4* __restrict__ he,
                            const float*  __restrict__ ulw, const float* __restrict__ ilw)
{
    int i = blockIdx.x * blockDim.x + threadIdx.x;

    // degree histogram: 4 edges per thread (return unused -> REDG)
    int e0 = i * 4;
    if (e0 + 3 < E) {
        int4 r4 = __ldg((const int4*)(row + e0));
        atomicAdd(&g_deg[r4.x], 1);
        atomicAdd(&g_deg[r4.y], 1);
        atomicAdd(&g_deg[r4.z], 1);
        atomicAdd(&g_deg[r4.w], 1);
    } else if (e0 < E) {
        for (int e = e0; e < E; e++) atomicAdd(&g_deg[__ldg(row + e)], 1);
    }

    if (i >= NH4) return;
    int rw  = i >> 3;
    int sub = i & 7;

    const float4* base;
    const float4* sem;
    int r;
    float a;
    if (rw < U_CNT) { a = sigm(__ldg(ulw)); base = ue; sem = se; r = rw; }
    else            { a = sigm(__ldg(ilw)); base = ie; sem = he; r = rw - U_CNT; }

    float4 b0 = __ldcs(&base[r * ROW_F4 + sub * 2]);
    float4 b1 = __ldcs(&base[r * ROW_F4 + sub * 2 + 1]);
    float4 s0 = __ldcs(&sem [r * ROW_F4 + sub * 2]);
    float4 s1 = __ldcs(&sem [r * ROW_F4 + sub * 2 + 1]);

    float xs[8] = { s0.x, s0.y, s0.z, s0.w, s1.x, s1.y, s1.z, s1.w };
    float xb[8] = { b0.x, b0.y, b0.z, b0.w, b1.x, b1.y, b1.z, b1.w };
    float x[8];
    #pragma unroll
    for (int k = 0; k < 8; k++) x[k] = a * xb[k] + (1.0f - a) * xs[k];

    g_sem[i]   = pack8(xs);
    g_Lh[0][i] = pack8(x);
}

// ---------------------------------------------------------------------------
// MERGED scan1+scan3: block scan of degrees + degree bins; resident-grid
// barrier (all 196 blocks co-resident via __launch_bounds__(1024,2) -> 2
// CTAs/SM x 148 = 296 >= 196, so the spin cannot deadlock); last-arriving
// block scans the 196 block sums + both bin sets; release; then ALL blocks
// finalize ptr/cursor/order and re-zero g_deg. Barrier counters self-reset.
// ---------------------------------------------------------------------------
__global__ void __launch_bounds__(SCAN_BLK, 2) k_scan13()
{
    __shared__ int sw[32];
    __shared__ int sbuf[256];
    __shared__ int isLast;
    int i    = blockIdx.x * SCAN_BLK + threadIdx.x;
    int lane = threadIdx.x & 31;
    int wid  = threadIdx.x >> 5;

    int v = (i < N_CNT) ? g_deg[i] : 0;

    // warp inclusive scan
    int x = v;
    #pragma unroll
    for (int off = 1; off < 32; off <<= 1) {
        int y = __shfl_up_sync(0xffffffffu, x, off);
        if (lane >= off) x += y;
    }
    if (lane == 31) sw[wid] = x;
    __syncthreads();

    if (wid == 0) {
        int wv = sw[lane];
        int wx = wv;
        #pragma unroll
        for (int off = 1; off < 32; off <<= 1) {
            int y = __shfl_up_sync(0xffffffffu, wx, off);
            if (lane >= off) wx += y;
        }
        sw[lane] = wx - wv;
    }
    __syncthreads();

    int excl_local = x + sw[wid] - v;               // exclusive, block-local
    if (threadIdx.x == SCAN_BLK - 1) g_bsum[blockIdx.x] = x + sw[wid];

    // per-partition degree-bin histogram (g_dbin == 0 on entry, invariant)
    if (i < N_CNT) {
        int d = v < DBINS ? v : DBINS - 1;
        atomicAdd(&g_dbin[i < U_CNT ? 0 : 1][d], 1);
    }

    // ---- barrier arrive ----
    __threadfence();
    __syncthreads();
    if (threadIdx.x == 0)
        isLast = (atomicAdd(&g_tick, 1) == (int)gridDim.x - 1);
    __syncthreads();

    if (isLast) {
        int t = threadIdx.x;

        // exclusive scan of block sums (196 values)
        int v2 = (t < SCAN_NB) ? g_bsum[t] : 0;
        if (t < 256) sbuf[t] = v2;
        __syncthreads();
        for (int off = 1; off < 256; off <<= 1) {
            int u = (t < 256 && t >= off) ? sbuf[t - off] : 0;
            __syncthreads();
            if (t < 256) sbuf[t] += u;
            __syncthreads();
        }
        if (t < SCAN_NB) g_bsum[t] = sbuf[t] - v2;
        if (t == SCAN_NB - 1) g_ptr[N_CNT] = sbuf[t];
        __syncthreads();

        // exclusive scans of the two degree-bin sets
        #pragma unroll
        for (int part = 0; part < 2; part++) {
            int v3 = (t < DBINS) ? g_dbin[part][t] : 0;
            if (t < 256) sbuf[t] = v3;
            __syncthreads();
            for (int off = 1; off < 256; off <<= 1) {
                int u = (t < 256 && t >= off) ? sbuf[t - off] : 0;
                __syncthreads();
                if (t < 256) sbuf[t] += u;
                __syncthreads();
            }
            if (t < DBINS) g_dbin[part][t] = sbuf[t] - v3;
            __syncthreads();
        }

        __threadfence();
        __syncthreads();
        if (t == 0) { g_tick = 0; atomicExch(&g_rel, 1); }   // release
    } else {
        // ---- barrier wait ----
        if (threadIdx.x == 0) {
            while (atomicAdd(&g_rel, 0) == 0) __nanosleep(200);
        }
        __syncthreads();
        __threadfence();
    }

    // ---- phase C (all blocks): finalize ptr/cursor; counting-sort rows ----
    if (i < N_CNT) {
        int p = excl_local + g_bsum[blockIdx.x];
        g_ptr[i]    = p;
        g_cursor[i] = p;
        int d = v < DBINS ? v : DBINS - 1;
        if (i < U_CNT) {
            int pos = atomicAdd(&g_dbin[0][d], 1);
            g_order[U_CNT - 1 - pos] = i;
        } else {
            int pos = atomicAdd(&g_dbin[1][d], 1);
            g_order[U_CNT + I_CNT - 1 - pos] = i;
        }
        g_deg[i] = 0;             // restore invariant
    }

    // ---- barrier depart (last departer resets for next replay) ----
    __syncthreads();
    if (threadIdx.x == 0) {
        if (atomicAdd(&g_tick2, 1) == (int)gridDim.x - 1) {
            g_tick2 = 0;
            g_rel   = 0;
        }
    }
}

// ---------------------------------------------------------------------------
// LEAN user-edge scatter (no fused init -> low regs, high occupancy, max
// atomic concurrency). Re-zeroes BOTH g_dbin partitions.
// ---------------------------------------------------------------------------
__global__ void k_scatU(const int*   __restrict__ row, const int* __restrict__ col,
                        const float* __restrict__ val, int E)
{
    int i = blockIdx.x * blockDim.x + threadIdx.x;
    if (blockIdx.x == 0 && threadIdx.x < DBINS) {
        ((int*)g_dbin)[threadIdx.x]         = 0;   // user bins
        ((int*)g_dbin)[threadIdx.x + DBINS] = 0;   // item bins
    }

    int e0 = i * 4;
    if (e0 >= E) return;
    if (e0 + 3 < E) {
        int4   r4 = __ldg((const int4*)(row + e0));
        int4   c4 = __ldg((const int4*)(col + e0));
        float4 v4 = __ldg((const float4*)(val + e0));
        int r[4] = { r4.x, r4.y, r4.z, r4.w };
        int c[4] = { c4.x, c4.y, c4.z, c4.w };
        float v[4] = { v4.x, v4.y, v4.z, v4.w };
        int p[4];
        bool m[4];
        #pragma unroll
        for (int k = 0; k < 4; k++) {
            m[k] = (r[k] < U_CNT);
            p[k] = m[k] ? atomicAdd(&g_cursor[r[k]], 1) : 0;
        }
        #pragma unroll
        for (int k = 0; k < 4; k++) {
            if (m[k]) {
                int q = __float2int_rn(v[k] * VAL_ENC_SCALE);
                q = q < 16383 ? q : 16383;
                g_csr[p[k]] = (unsigned)c[k] | ((unsigned)q << 18);
            }
        }
    } else {
        for (int e = e0; e < E; e++) {
            int r = __ldg(row + e);
            if (r >= U_CNT) continue;
            int pp = atomicAdd(&g_cursor[r], 1);
            int q = __float2int_rn(__ldg(val + e) * VAL_ENC_SCALE);
            q = q < 16383 ? q : 16383;
            g_csr[pp] = (unsigned)__ldg(col + e) | ((unsigned)q << 18);
        }
    }
}

// ---------------------------------------------------------------------------
// FUSED: spmm layer-1 over USER rows  ∥  scatter of ITEM edges.
// Role by bid: bid%3==0 && bid/3 < SPMM_U_BLOCKS -> spmm; else scatter with
// sb = bid - min(ceil(bid/3), SPMM_U_BLOCKS).
// ---------------------------------------------------------------------------
__global__ void k_spmmU1_scatI(const int*   __restrict__ row, const int* __restrict__ col,
                               const float* __restrict__ val, int E,
                               const float* __restrict__ ulw, const float* __restrict__ ilw)
{
    int bid = blockIdx.x;
    bool is_spmm = (bid % 3 == 0) && (bid / 3 < SPMM_U_BLOCKS);
    if (is_spmm) {
        int t = (bid / 3) * blockDim.x + threadIdx.x;
        int g = t >> 3;
        if (g >= U_CNT) return;
        int sub = t & 7;
        int rw = __ldg(&g_order[g]);
        spmm_row_do(1, rw, sub, ulw, ilw);
        return;
    }
    int nsp = (bid + 2) / 3;
    if (nsp > SPMM_U_BLOCKS) nsp = SPMM_U_BLOCKS;
    int sb = bid - nsp;
    int i = sb * blockDim.x + threadIdx.x;

    int e0 = i * 4;
    if (e0 >= E) return;
    if (e0 + 3 < E) {
        int4   r4 = __ldg((const int4*)(row + e0));
        int4   c4 = __ldg((const int4*)(col + e0));
        float4 v4 = __ldg((const float4*)(val + e0));
        int r[4] = { r4.x, r4.y, r4.z, r4.w };
        int c[4] = { c4.x, c4.y, c4.z, c4.w };
        float v[4] = { v4.x, v4.y, v4.z, v4.w };
        int p[4];
        bool m[4];
        #pragma unroll
        for (int k = 0; k < 4; k++) {
            m[k] = (r[k] >= U_CNT);
            p[k] = m[k] ? atomicAdd(&g_cursor[r[k]], 1) : 0;
        }
        #pragma unroll
        for (int k = 0; k < 4; k++) {
            if (m[k]) {
                int q = __float2int_rn(v[k] * VAL_ENC_SCALE);
                q = q < 16383 ? q : 16383;
                g_csr[p[k]] = (unsigned)c[k] | ((unsigned)q << 18);
            }
        }
    } else {
        for (int e = e0; e < E; e++) {
            int r = __ldg(row + e);
            if (r < U_CNT) continue;
            int pp = atomicAdd(&g_cursor[r], 1);
            int q = __float2int_rn(__ldg(val + e) * VAL_ENC_SCALE);
            q = q < 16383 ? q : 16383;
            g_csr[pp] = (unsigned)__ldg(col + e) | ((unsigned)q << 18);
        }
    }
}

// ---------------------------------------------------------------------------
// SpMM layer-1 over ITEM rows only.
// ---------------------------------------------------------------------------
__global__ void k_spmmI1(const float* __restrict__ ulw, const float* __restrict__ ilw)
{
    int t = blockIdx.x * blockDim.x + threadIdx.x;
    int g = t >> 3;
    if (g >= I_CNT) return;
    int sub = t & 7;
    int rw = __ldg(&g_order[U_CNT + g]);
    spmm_row_do(1, rw, sub, ulw, ilw);
}

// ---------------------------------------------------------------------------
// Full SpMM (layer 2) over all rows.
// ---------------------------------------------------------------------------
__global__ void k_spmm_fused(const float* __restrict__ ulw, const float* __restrict__ ilw,
                             int layer)
{
    int t = blockIdx.x * blockDim.x + threadIdx.x;
    int g = t >> 3;
    if (g >= N_CNT) return;
    int sub = t & 7;
    int rw = __ldg(&g_order[g]);
    spmm_row_do(layer, rw, sub, ulw, ilw);
}

// ---------------------------------------------------------------------------
// FUSED dot + on-demand layer 3 (fp32, never stored).
// ---------------------------------------------------------------------------
__device__ __forceinline__ void row_sum_with_l3(int rw, int sub, float a3,
                                                float* s)
{
    float acc[8];
    #pragma unroll
    for (int k = 0; k < 8; k++) acc[k] = 0.0f;
    gather_row(g_Lh[2], rw, sub, acc);

    float o[8];
    unpack8(__ldg(&g_sem[rw * ROW_H4 + sub]), o);

    #pragma unroll
    for (int k = 0; k < 8; k++) s[k] = a3 * acc[k] + (1.0f - a3) * o[k];

    #pragma unroll
    for (int l = 0; l < 3; l++) {
        float x[8];
        unpack8(__ldg(&g_Lh[l][rw * ROW_H4 + sub]), x);
        #pragma unroll
        for (int k = 0; k < 8; k++) s[k] += x[k];
    }
}

__global__ void k_dot3(const int* __restrict__ users, const int* __restrict__ items,
                       const float* __restrict__ ulw, const float* __restrict__ ilw,
                       float* __restrict__ out, int B)
{
    int t = blockIdx.x * blockDim.x + threadIdx.x;
    int b = t >> 3;
    if (b >= B) return;
    int sub = t & 7;

    int u  = __ldg(users + b);
    int it = __ldg(items + b) + U_CNT;

    float aU = sigm(__ldg(ulw + L_LAYERS));
    float aI = sigm(__ldg(ilw + L_LAYERS));

    float su[8], si[8];
    row_sum_with_l3(u,  sub, aU, su);
    row_sum_with_l3(it, sub, aI, si);

    float s = 0.0f;
    #pragma unroll
    for (int k = 0; k < 8; k++) s = fmaf(su[k], si[k], s);

    s += __shfl_down_sync(0xffffffffu, s, 4, 8);
    s += __shfl_down_sync(0xffffffffu, s, 2, 8);
    s += __shfl_down_sync(0xffffffffu, s, 1, 8);

    if (sub == 0) out[b] = s * (1.0f / ((L_LAYERS + 1) * (L_LAYERS + 1)));
}

// ---------------------------------------------------------------------------
// Launch sequence: hist+init | scan13 | scatU | spmmU1∥scatI | spmmI1 |
// spmm2 | dot3.   (7 launches)
// ---------------------------------------------------------------------------
extern "C" void kernel_launch(void* const* d_in, const int* in_sizes, int n_in,
                              void* d_out, int out_size)
{
    const float4* user_emb    = (const float4*)d_in[0];
    const float4* item_emb    = (const float4*)d_in[1];
    const float4* symptom_emb = (const float4*)d_in[2];
    const float4* herb_emb    = (const float4*)d_in[3];
    const float*  user_lw     = (const float*)d_in[4];
    const float*  item_lw     = (const float*)d_in[5];
    const float*  edge_val    = (const float*)d_in[6];
    const int*    edge_row    = (const int*)d_in[7];
    const int*    edge_col    = (const int*)d_in[8];
    const int*    users       = (const int*)d_in[9];
    const int*    items       = (const int*)d_in[10];

    int E = in_sizes[6];
    int B = in_sizes[9];

    const int TB = 256;
    int e4 = (E + 3) / 4;

    int hi_threads = (e4 > NH4 ? e4 : NH4);
    k_hist_init<<<(hi_threads + TB - 1) / TB, TB>>>(
        edge_row, E,
        user_emb, item_emb, symptom_emb, herb_emb, user_lw, item_lw);

    k_scan13<<<SCAN_NB, SCAN_BLK>>>();

    k_scatU<<<(e4 + TB - 1) / TB, TB>>>(edge_row, edge_col, edge_val, E);

    int scat_blocks = (e4 + TB - 1) / TB;
    int k5_blocks = SPMM_U_BLOCKS + scat_blocks;
    int need_for_spmm = (SPMM_U_BLOCKS - 1) * 3 + 1;
    if (k5_blocks < need_for_spmm) k5_blocks = need_for_spmm;
    k_spmmU1_scatI<<<k5_blocks, TB>>>(edge_row, edge_col, edge_val, E,
                                      user_lw, item_lw);

    k_spmmI1<<<(I_CNT * 8 + TB - 1) / TB, TB>>>(user_lw, item_lw);

    k_spmm_fused<<<(N_CNT * 8 + TB - 1) / TB, TB>>>(user_lw, item_lw, 2);

    k_dot3<<<(B * 8 + TB - 1) / TB, TB>>>(users, items, user_lw, item_lw,
                                          (float*)d_out, B);
}